// round 10
// baseline (speedup 1.0000x reference)
#include <cuda_runtime.h>
#include <cstdint>

// ---------------- problem constants ----------------
#define BATCH     32
#define LEN       220500
#define HOP       512
#define PADW      1024
#define FREQ      1025
#define NFRAMES   431
#define NBT       (BATCH * NFRAMES)     // 13792
#define KDIM      1024                  // folded K
#define NPAD      13824                 // 108 * 128
#define MDIM      1024                  // GEMM M (bins 0..1023; bin 1024 separate)
#define NFFT      2048

#define BM        256
#define BN        128
#define ASTR      264                   // A smem row stride (264 % 32 == 8 -> conflict-free)
#define BSTR      136                   // B smem row stride
#define NKT       (KDIM / 16)           // 64 k-tiles
#define STAGES    6
#define ASZ       (16 * ASTR)           // 4224 floats
#define BSZ       (16 * BSTR)           // 2176 floats
#define STAGE_FLOATS (ASZ + BSZ)        // 6400 floats (25600 B)
#define SMEM_BYTES (STAGES * STAGE_FLOATS * 4)   // 153600 B

// ---------------- device scratch ----------------
__device__ float g_Ut [KDIM * NPAD];
__device__ float g_Vt [KDIM * NPAD];
__device__ float g_Wct[KDIM * MDIM];
__device__ float g_Wst[KDIM * MDIM];

__device__ __forceinline__ float tf32r(float x) {
    uint32_t u; asm("cvt.rna.tf32.f32 %0, %1;" : "=r"(u) : "f"(x));
    return __uint_as_float(u);
}
__device__ __forceinline__ void cpa16(uint32_t s, const void* g) {
    asm volatile("cp.async.cg.shared.global [%0], [%1], 16;" :: "r"(s), "l"(g));
}
__device__ __forceinline__ void cpa_commit() {
    asm volatile("cp.async.commit_group;" ::: "memory");
}
template <int N>
__device__ __forceinline__ void cpa_wait() {
    asm volatile("cp.async.wait_group %0;" :: "n"(N) : "memory");
}

// ---------------- kernel 1: weight transpose (coalesced 32x32 tiles) ----------------
// g_Wct[j][k] = tf32(wcos[k][j+1]) for k in [0,1024), j in [0,1024)
__global__ void __launch_bounds__(256) wprep_kernel(const float* __restrict__ wcos,
                                                    const float* __restrict__ wsin) {
    __shared__ float sc[32][33];
    __shared__ float ss[32][33];
    const int kt = blockIdx.y * 32;
    const int jt = blockIdx.x * 32;
    const int tx = threadIdx.x & 31;
    const int ty = threadIdx.x >> 5;
#pragma unroll
    for (int tt = 0; tt < 4; ++tt) {
        int kl = ty * 4 + tt;                          // k-local
        size_t src = (size_t)(kt + kl) * NFFT + jt + tx + 1;
        sc[kl][tx] = tf32r(wcos[src]);
        ss[kl][tx] = tf32r(wsin[src]);
    }
    __syncthreads();
#pragma unroll
    for (int tt = 0; tt < 4; ++tt) {
        int jl = ty * 4 + tt;                          // j-local
        size_t dst = (size_t)(jt + jl) * MDIM + kt + tx;
        g_Wct[dst] = sc[tx][jl];
        g_Wst[dst] = ss[tx][jl];
    }
}

// ---------------- kernel 2: fused reflect-pad + fold + transpose ----------------
__global__ void __launch_bounds__(256) frame_kernel(const float* __restrict__ x) {
    __shared__ float su[32][33];
    __shared__ float sv[32][33];
    const int b  = blockIdx.z;
    const int t0 = blockIdx.x * 32;
    const int j0 = blockIdx.y * 32;
    const int tx = threadIdx.x & 31;
    const int ty = threadIdx.x >> 5;
    const float* __restrict__ xb = x + (size_t)b * LEN;

#pragma unroll
    for (int tt = 0; tt < 4; ++tt) {
        int tl = ty * 4 + tt;
        int t = t0 + tl;
        float u = 0.f, v = 0.f;
        if (t < NFRAMES) {
            int j = j0 + tx;
            int base = t * HOP - PADW;
            int m1 = base + j + 1;
            int m2 = base + 2047 - j;
            m1 = m1 < 0 ? -m1 : (m1 >= LEN ? 2 * LEN - 2 - m1 : m1);
            m2 = m2 < 0 ? -m2 : (m2 >= LEN ? 2 * LEN - 2 - m2 : m2);
            float a  = xb[m1];
            float bb = xb[m2];
            u = a + bb;
            v = a - bb;
            if (j == 1023) { u = a; v = 0.f; }
        }
        su[tl][tx] = tf32r(u);
        sv[tl][tx] = tf32r(v);
    }
    __syncthreads();

    int t = t0 + tx;
    if (t >= NFRAMES) return;
    int bt = b * NFRAMES + t;
#pragma unroll
    for (int jj = 0; jj < 4; ++jj) {
        int jl = ty * 4 + jj;
        int j = j0 + jl;
        g_Ut[(size_t)j * NPAD + bt] = su[tx][jl];
        g_Vt[(size_t)j * NPAD + bt] = sv[tx][jl];
    }
}

// ---------------- kernel 3: Nyquist bin k=1024 (fp32 exact) ----------------
__global__ void __launch_bounds__(256) nyq_kernel(const float* __restrict__ x,
                                                  const float* __restrict__ wcos,
                                                  const float* __restrict__ wsin,
                                                  float* __restrict__ out) {
    __shared__ float wc[NFFT];
    __shared__ float ws[NFFT];
    for (int i = threadIdx.x; i < NFFT; i += 256) {
        wc[i] = wcos[(size_t)1024 * NFFT + i];
        ws[i] = wsin[(size_t)1024 * NFFT + i];
    }
    __syncthreads();
    int bt = blockIdx.x * 256 + threadIdx.x;
    if (bt >= NBT) return;
    int b = bt / NFRAMES;
    int t = bt - b * NFRAMES;
    const float* __restrict__ xb = x + (size_t)b * LEN;
    int base = t * HOP - PADW;
    float sr = 0.f, si = 0.f;
    for (int s = 0; s < NFFT; ++s) {
        int m = base + s;
        m = m < 0 ? -m : (m >= LEN ? 2 * LEN - 2 - m : m);
        float f = xb[m];
        sr += wc[s] * f;
        si += ws[s] * f;
    }
    size_t o = (((size_t)b * FREQ + 1024) * NFRAMES + t) << 1;
    out[o]     = sr;
    out[o + 1] = -si;
}

// ---------------- kernel 4: TF32 mma.sync GEMM, 256x128 tile, 6-stage ring ----------------
#define MMA_TF32(d, a, b)                                                       \
    asm volatile(                                                               \
        "mma.sync.aligned.m16n8k8.row.col.f32.tf32.tf32.f32 "                   \
        "{%0,%1,%2,%3},{%4,%5,%6,%7},{%8,%9},{%0,%1,%2,%3};"                    \
        : "+f"(d[0]), "+f"(d[1]), "+f"(d[2]), "+f"(d[3])                        \
        : "r"(a[0]), "r"(a[1]), "r"(a[2]), "r"(a[3]), "r"(b[0]), "r"(b[1]))

__global__ void __launch_bounds__(512, 1) gemm_kernel(float* __restrict__ out) {
    extern __shared__ float smem[];
    const int z = blockIdx.z;
    const float* __restrict__ W = z ? g_Wst : g_Wct;
    const float* __restrict__ X = z ? g_Vt  : g_Ut;

    const int tid  = threadIdx.x;
    const int warp = tid >> 5, lane = tid & 31;
    const int wm = warp & 3;            // 0..3 : 64-row slabs (256 M)
    const int wn = warp >> 2;           // 0..3 : 32-col slabs (128 N)
    const int g  = lane >> 2;
    const int tg = lane & 3;
    const int m0 = blockIdx.y * BM;
    const int n0 = blockIdx.x * BN;

    // cp.async: A = 16 x 256 floats (1024 f4): rows rA0, rA0+8; B = 16 x 128 (512 f4)
    const int rA0 = tid >> 6, cA = (tid & 63) * 4;    // rows 0..7
    const int rA1 = rA0 + 8;                          // rows 8..15
    const int rB  = tid >> 5, cB = (tid & 31) * 4;    // rows 0..15
    const float* A0 = W + (size_t)rA0 * MDIM + m0 + cA;
    const float* A1 = W + (size_t)rA1 * MDIM + m0 + cA;
    const float* B0 = X + (size_t)rB  * NPAD + n0 + cB;

    const uint32_t sbase = (uint32_t)__cvta_generic_to_shared(smem);
    const uint32_t oA0 = (uint32_t)((rA0 * ASTR + cA) * 4);
    const uint32_t oA1 = (uint32_t)((rA1 * ASTR + cA) * 4);
    const uint32_t oB0 = (uint32_t)((ASZ + rB * BSTR + cB) * 4);

    auto issue = [&](int c, int slot) {
        size_t koff = (size_t)c * 16;
        uint32_t sb = sbase + (uint32_t)(slot * STAGE_FLOATS * 4);
        cpa16(sb + oA0, A0 + koff * MDIM);
        cpa16(sb + oA1, A1 + koff * MDIM);
        cpa16(sb + oB0, B0 + koff * NPAD);
        cpa_commit();
    };

    float acc[4][4][4];
#pragma unroll
    for (int i = 0; i < 4; ++i)
#pragma unroll
        for (int j = 0; j < 4; ++j)
#pragma unroll
            for (int c = 0; c < 4; ++c) acc[i][j][c] = 0.f;

    const int abase = wm * 64 + g;
    const int bbase = wn * 32 + g;

    // prologue: fill STAGES-1 = 5 stages
#pragma unroll
    for (int p = 0; p < STAGES - 1; ++p) issue(p, p);

    int slot = 0;                 // consume slot (c % STAGES)
    int islot = STAGES - 1;       // issue slot
    for (int c = 0; c < NKT; ++c) {
        const int rem = NKT - 1 - c;        // groups pending beyond c
        if (rem >= 4)      cpa_wait<4>();
        else if (rem == 3) cpa_wait<3>();
        else if (rem == 2) cpa_wait<2>();
        else if (rem == 1) cpa_wait<1>();
        else               cpa_wait<0>();
        __syncthreads();
        if (c + STAGES - 1 < NKT) issue(c + STAGES - 1, islot);

        const uint32_t* Asu = (const uint32_t*)(smem + slot * STAGE_FLOATS);
        const uint32_t* Bsu = Asu + ASZ;
#pragma unroll
        for (int s = 0; s < 2; ++s) {
            const int krow = 8 * s + tg;
            uint32_t bf[4][2];
#pragma unroll
            for (int j = 0; j < 4; ++j) {
                bf[j][0] = Bsu[krow * BSTR + bbase + 8 * j];
                bf[j][1] = Bsu[(krow + 4) * BSTR + bbase + 8 * j];
            }
#pragma unroll
            for (int i = 0; i < 4; ++i) {
                uint32_t af[4];
                const int mcol = abase + 16 * i;
                af[0] = Asu[krow * ASTR + mcol];
                af[1] = Asu[krow * ASTR + mcol + 8];
                af[2] = Asu[(krow + 4) * ASTR + mcol];
                af[3] = Asu[(krow + 4) * ASTR + mcol + 8];
#pragma unroll
                for (int j = 0; j < 4; ++j) MMA_TF32(acc[i][j], af, bf[j]);
            }
        }
        slot  = (slot  == STAGES - 1) ? 0 : slot + 1;
        islot = (islot == STAGES - 1) ? 0 : islot + 1;
    }

    // epilogue: out[b][k][t][z], imag negated; k always < 1024 < FREQ
    int btc[4][2], bc[4][2], tc[4][2];
#pragma unroll
    for (int j = 0; j < 4; ++j)
#pragma unroll
        for (int q = 0; q < 2; ++q) {
            int bt = n0 + wn * 32 + 8 * j + 2 * tg + q;
            btc[j][q] = bt;
            bc[j][q] = bt / NFRAMES;
            tc[j][q] = bt - bc[j][q] * NFRAMES;
        }
#pragma unroll
    for (int i = 0; i < 4; ++i) {
#pragma unroll
        for (int h = 0; h < 2; ++h) {
            int k = m0 + wm * 64 + 16 * i + g + 8 * h;
#pragma unroll
            for (int j = 0; j < 4; ++j)
#pragma unroll
                for (int q = 0; q < 2; ++q) {
                    if (btc[j][q] >= NBT) continue;
                    float v = acc[i][j][2 * h + q];
                    if (z) v = -v;
                    out[((((size_t)bc[j][q] * FREQ + k) * NFRAMES + tc[j][q]) << 1) + z] = v;
                }
        }
    }
}

// ---------------- launch ----------------
extern "C" void kernel_launch(void* const* d_in, const int* in_sizes, int n_in,
                              void* d_out, int out_size) {
    const float* x    = (const float*)d_in[0];
    const float* wcos = (const float*)d_in[1];
    const float* wsin = (const float*)d_in[2];
    float* out = (float*)d_out;

    cudaFuncSetAttribute(gemm_kernel, cudaFuncAttributeMaxDynamicSharedMemorySize, SMEM_BYTES);

    wprep_kernel<<<dim3(KDIM / 32, MDIM / 32), 256>>>(wcos, wsin);
    frame_kernel<<<dim3((NFRAMES + 31) / 32, KDIM / 32, BATCH), 256>>>(x);
    nyq_kernel<<<(NBT + 255) / 256, 256>>>(x, wcos, wsin, out);
    gemm_kernel<<<dim3(NPAD / BN, MDIM / BM, 2), 512, SMEM_BYTES>>>(out);
}

// round 11
// speedup vs baseline: 1.7936x; 1.7936x over previous
#include <cuda_runtime.h>
#include <cstdint>

// ---------------- problem constants ----------------
#define BATCH     32
#define LEN       220500
#define HOP       512
#define PADW      1024
#define FREQ      1025
#define NFRAMES   431
#define NBT       (BATCH * NFRAMES)     // 13792
#define KDIM      1024                  // folded K
#define NPAD      13824                 // 108 * 128
#define MDIM      1024                  // GEMM M (bins 0..1023; bin 1024 separate)
#define NFFT      2048
#define SSTR      136                   // smem row stride (floats) -> conflict-free frags
#define NKT       (KDIM / 16)           // 64 k-tiles
#define STAGES    5
#define STAGE_FLOATS (2 * 16 * SSTR)    // A+B per stage = 4352 floats (17408 B)
#define SMEM_BYTES (STAGES * STAGE_FLOATS * 4)   // 87040 B  (2 CTAs/SM = 174 KB < 228 KB)

// ---------------- device scratch ----------------
__device__ float g_Ut [KDIM * NPAD];
__device__ float g_Vt [KDIM * NPAD];
__device__ float g_Wct[KDIM * MDIM];
__device__ float g_Wst[KDIM * MDIM];

__device__ __forceinline__ float tf32r(float x) {
    uint32_t u; asm("cvt.rna.tf32.f32 %0, %1;" : "=r"(u) : "f"(x));
    return __uint_as_float(u);
}
__device__ __forceinline__ void cpa16(uint32_t s, const void* g) {
    asm volatile("cp.async.cg.shared.global [%0], [%1], 16;" :: "r"(s), "l"(g));
}
__device__ __forceinline__ void cpa_commit() {
    asm volatile("cp.async.commit_group;" ::: "memory");
}
template <int N>
__device__ __forceinline__ void cpa_wait() {
    asm volatile("cp.async.wait_group %0;" :: "n"(N) : "memory");
}

// ---------------- kernel 1: weight transpose (coalesced 32x32 tiles) ----------------
__global__ void __launch_bounds__(256) wprep_kernel(const float* __restrict__ wcos,
                                                    const float* __restrict__ wsin) {
    __shared__ float sc[32][33];
    __shared__ float ss[32][33];
    const int kt = blockIdx.y * 32;
    const int jt = blockIdx.x * 32;
    const int tx = threadIdx.x & 31;
    const int ty = threadIdx.x >> 5;
#pragma unroll
    for (int tt = 0; tt < 4; ++tt) {
        int kl = ty * 4 + tt;
        size_t src = (size_t)(kt + kl) * NFFT + jt + tx + 1;
        sc[kl][tx] = tf32r(wcos[src]);
        ss[kl][tx] = tf32r(wsin[src]);
    }
    __syncthreads();
#pragma unroll
    for (int tt = 0; tt < 4; ++tt) {
        int jl = ty * 4 + tt;
        size_t dst = (size_t)(jt + jl) * MDIM + kt + tx;
        g_Wct[dst] = sc[tx][jl];
        g_Wst[dst] = ss[tx][jl];
    }
}

// ---------------- kernel 2: fused reflect-pad + fold + transpose ----------------
__global__ void __launch_bounds__(256) frame_kernel(const float* __restrict__ x) {
    __shared__ float su[32][33];
    __shared__ float sv[32][33];
    const int b  = blockIdx.z;
    const int t0 = blockIdx.x * 32;
    const int j0 = blockIdx.y * 32;
    const int tx = threadIdx.x & 31;
    const int ty = threadIdx.x >> 5;
    const float* __restrict__ xb = x + (size_t)b * LEN;

#pragma unroll
    for (int tt = 0; tt < 4; ++tt) {
        int tl = ty * 4 + tt;
        int t = t0 + tl;
        float u = 0.f, v = 0.f;
        if (t < NFRAMES) {
            int j = j0 + tx;
            int base = t * HOP - PADW;
            int m1 = base + j + 1;
            int m2 = base + 2047 - j;
            m1 = m1 < 0 ? -m1 : (m1 >= LEN ? 2 * LEN - 2 - m1 : m1);
            m2 = m2 < 0 ? -m2 : (m2 >= LEN ? 2 * LEN - 2 - m2 : m2);
            float a  = xb[m1];
            float bb = xb[m2];
            u = a + bb;
            v = a - bb;
            if (j == 1023) { u = a; v = 0.f; }
        }
        su[tl][tx] = tf32r(u);
        sv[tl][tx] = tf32r(v);
    }
    __syncthreads();

    int t = t0 + tx;
    if (t >= NFRAMES) return;
    int bt = b * NFRAMES + t;
#pragma unroll
    for (int jj = 0; jj < 4; ++jj) {
        int jl = ty * 4 + jj;
        int j = j0 + jl;
        g_Ut[(size_t)j * NPAD + bt] = su[tx][jl];
        g_Vt[(size_t)j * NPAD + bt] = sv[tx][jl];
    }
}

// ---------------- kernel 3: Nyquist bin k=1024, one warp per frame ----------------
__global__ void __launch_bounds__(256) nyq_kernel(const float* __restrict__ x,
                                                  const float* __restrict__ wcos,
                                                  const float* __restrict__ wsin,
                                                  float* __restrict__ out) {
    __shared__ float wc[NFFT];
    __shared__ float ws[NFFT];
    for (int i = threadIdx.x; i < NFFT; i += 256) {
        wc[i] = wcos[(size_t)1024 * NFFT + i];
        ws[i] = wsin[(size_t)1024 * NFFT + i];
    }
    __syncthreads();
    const int lane = threadIdx.x & 31;
    const int bt = blockIdx.x * 8 + (threadIdx.x >> 5);
    if (bt >= NBT) return;
    int b = bt / NFRAMES;
    int t = bt - b * NFRAMES;
    const float* __restrict__ xb = x + (size_t)b * LEN;
    int base = t * HOP - PADW;
    float sr = 0.f, si = 0.f;
#pragma unroll 4
    for (int s = lane; s < NFFT; s += 32) {
        int m = base + s;
        m = m < 0 ? -m : (m >= LEN ? 2 * LEN - 2 - m : m);
        float f = xb[m];
        sr += wc[s] * f;
        si += ws[s] * f;
    }
#pragma unroll
    for (int o = 16; o > 0; o >>= 1) {
        sr += __shfl_xor_sync(0xffffffffu, sr, o);
        si += __shfl_xor_sync(0xffffffffu, si, o);
    }
    if (lane == 0) {
        size_t o = (((size_t)b * FREQ + 1024) * NFRAMES + t) << 1;
        out[o]     = sr;
        out[o + 1] = -si;
    }
}

// ---------------- kernel 4: TF32 mma.sync GEMM, 128x128, 5-stage, m-fast raster ----------------
#define MMA_TF32(d, a, b)                                                       \
    asm volatile(                                                               \
        "mma.sync.aligned.m16n8k8.row.col.f32.tf32.tf32.f32 "                   \
        "{%0,%1,%2,%3},{%4,%5,%6,%7},{%8,%9},{%0,%1,%2,%3};"                    \
        : "+f"(d[0]), "+f"(d[1]), "+f"(d[2]), "+f"(d[3])                        \
        : "r"(a[0]), "r"(a[1]), "r"(a[2]), "r"(a[3]), "r"(b[0]), "r"(b[1]))

__global__ void __launch_bounds__(256, 2) gemm_kernel(float* __restrict__ out) {
    extern __shared__ float smem[];
    const int z = blockIdx.z;
    const float* __restrict__ W = z ? g_Wst : g_Wct;
    const float* __restrict__ X = z ? g_Vt  : g_Ut;

    const int tid  = threadIdx.x;
    const int warp = tid >> 5, lane = tid & 31;
    const int wm = warp & 1;
    const int wn = warp >> 1;
    const int g  = lane >> 2;
    const int tg = lane & 3;
    // m is the FAST block index -> concurrent CTAs share B n-tiles (L2 reuse)
    const int m0 = blockIdx.x * 128;
    const int n0 = blockIdx.y * 128;

    const int r0c = tid >> 5, c0c = (tid & 31) * 4;
    const int r1c = r0c + 8;
    const float* A0 = W + (size_t)r0c * MDIM + m0 + c0c;
    const float* A1 = W + (size_t)r1c * MDIM + m0 + c0c;
    const float* B0 = X + (size_t)r0c * NPAD + n0 + c0c;
    const float* B1 = X + (size_t)r1c * NPAD + n0 + c0c;

    const uint32_t sbase = (uint32_t)__cvta_generic_to_shared(smem);
    const uint32_t oA0 = (uint32_t)((r0c * SSTR + c0c) * 4);
    const uint32_t oA1 = (uint32_t)((r1c * SSTR + c0c) * 4);
    const uint32_t oB0 = oA0 + 16 * SSTR * 4;
    const uint32_t oB1 = oA1 + 16 * SSTR * 4;

    auto issue = [&](int c, int slot) {
        size_t koff = (size_t)c * 16;
        uint32_t sb = sbase + (uint32_t)(slot * STAGE_FLOATS * 4);
        cpa16(sb + oA0, A0 + koff * MDIM);
        cpa16(sb + oA1, A1 + koff * MDIM);
        cpa16(sb + oB0, B0 + koff * NPAD);
        cpa16(sb + oB1, B1 + koff * NPAD);
        cpa_commit();
    };

    float acc[4][4][4];
#pragma unroll
    for (int i = 0; i < 4; ++i)
#pragma unroll
        for (int j = 0; j < 4; ++j)
#pragma unroll
            for (int c = 0; c < 4; ++c) acc[i][j][c] = 0.f;

    const int abase = wm * 64 + g;
    const int bbase = wn * 32 + g;

#pragma unroll
    for (int p = 0; p < STAGES - 1; ++p) issue(p, p);

    int slot = 0;
    int islot = STAGES - 1;
    for (int c = 0; c < NKT; ++c) {
        const int rem = NKT - 1 - c;
        if (rem >= 3)      cpa_wait<3>();
        else if (rem == 2) cpa_wait<2>();
        else if (rem == 1) cpa_wait<1>();
        else               cpa_wait<0>();
        __syncthreads();
        if (c + STAGES - 1 < NKT) issue(c + STAGES - 1, islot);

        const uint32_t* Asu = (const uint32_t*)(smem + slot * STAGE_FLOATS);
        const uint32_t* Bsu = Asu + 16 * SSTR;
#pragma unroll
        for (int s = 0; s < 2; ++s) {
            const int krow = 8 * s + tg;
            uint32_t bf[4][2];
#pragma unroll
            for (int j = 0; j < 4; ++j) {
                bf[j][0] = Bsu[krow * SSTR + bbase + 8 * j];
                bf[j][1] = Bsu[(krow + 4) * SSTR + bbase + 8 * j];
            }
#pragma unroll
            for (int i = 0; i < 4; ++i) {
                uint32_t af[4];
                const int mcol = abase + 16 * i;
                af[0] = Asu[krow * SSTR + mcol];
                af[1] = Asu[krow * SSTR + mcol + 8];
                af[2] = Asu[(krow + 4) * SSTR + mcol];
                af[3] = Asu[(krow + 4) * SSTR + mcol + 8];
#pragma unroll
                for (int j = 0; j < 4; ++j) MMA_TF32(acc[i][j], af, bf[j]);
            }
        }
        slot  = (slot  == STAGES - 1) ? 0 : slot + 1;
        islot = (islot == STAGES - 1) ? 0 : islot + 1;
    }

    // epilogue: out[b][k][t][z], imag negated; k < 1024 always
    int btc[4][2], bc[4][2], tc[4][2];
#pragma unroll
    for (int j = 0; j < 4; ++j)
#pragma unroll
        for (int q = 0; q < 2; ++q) {
            int bt = n0 + wn * 32 + 8 * j + 2 * tg + q;
            btc[j][q] = bt;
            bc[j][q] = bt / NFRAMES;
            tc[j][q] = bt - bc[j][q] * NFRAMES;
        }
#pragma unroll
    for (int i = 0; i < 4; ++i) {
#pragma unroll
        for (int h = 0; h < 2; ++h) {
            int k = m0 + wm * 64 + 16 * i + g + 8 * h;
#pragma unroll
            for (int j = 0; j < 4; ++j)
#pragma unroll
                for (int q = 0; q < 2; ++q) {
                    if (btc[j][q] >= NBT) continue;
                    float v = acc[i][j][2 * h + q];
                    if (z) v = -v;
                    out[((((size_t)bc[j][q] * FREQ + k) * NFRAMES + tc[j][q]) << 1) + z] = v;
                }
        }
    }
}

// ---------------- launch ----------------
extern "C" void kernel_launch(void* const* d_in, const int* in_sizes, int n_in,
                              void* d_out, int out_size) {
    const float* x    = (const float*)d_in[0];
    const float* wcos = (const float*)d_in[1];
    const float* wsin = (const float*)d_in[2];
    float* out = (float*)d_out;

    cudaFuncSetAttribute(gemm_kernel, cudaFuncAttributeMaxDynamicSharedMemorySize, SMEM_BYTES);

    wprep_kernel<<<dim3(KDIM / 32, MDIM / 32), 256>>>(wcos, wsin);
    frame_kernel<<<dim3((NFRAMES + 31) / 32, KDIM / 32, BATCH), 256>>>(x);
    nyq_kernel<<<(NBT + 7) / 8, 256>>>(x, wcos, wsin, out);
    gemm_kernel<<<dim3(MDIM / 128, NPAD / 128, 2), 256, SMEM_BYTES>>>(out);
}

// round 13
// speedup vs baseline: 1.8718x; 1.0436x over previous
#include <cuda_runtime.h>
#include <cstdint>

// ---------------- problem constants ----------------
#define BATCH     32
#define LEN       220500
#define HOP       512
#define PADW      1024
#define FREQ      1025
#define NFRAMES   431
#define NBT       (BATCH * NFRAMES)     // 13792
#define KDIM      1024                  // folded K
#define NPAD      13824                 // 108 * 128
#define MDIM      1024                  // GEMM M (bins 0..1023; bin 1024 separate)
#define NFFT      2048
#define SSTR      136                   // smem row stride (floats) -> conflict-free frags
#define NKT       (KDIM / 16)           // 64 k-tiles
#define STAGES    5
#define STAGE_FLOATS (2 * 16 * SSTR)    // A+B per stage = 4352 floats (17408 B)
#define SMEM_BYTES (STAGES * STAGE_FLOATS * 4)   // 87040 B (2 CTAs/SM)

// ---------------- device scratch ----------------
__device__ float g_Ut [KDIM * NPAD];
__device__ float g_Vt [KDIM * NPAD];
__device__ float g_Wct[KDIM * MDIM];
__device__ float g_Wst[KDIM * MDIM];

__device__ __forceinline__ float tf32r(float x) {
    uint32_t u; asm("cvt.rna.tf32.f32 %0, %1;" : "=r"(u) : "f"(x));
    return __uint_as_float(u);
}
__device__ __forceinline__ void cpa16(uint32_t s, const void* g) {
    asm volatile("cp.async.cg.shared.global [%0], [%1], 16;" :: "r"(s), "l"(g));
}
__device__ __forceinline__ void cpa_commit() {
    asm volatile("cp.async.commit_group;" ::: "memory");
}
template <int N>
__device__ __forceinline__ void cpa_wait() {
    asm volatile("cp.async.wait_group %0;" :: "n"(N) : "memory");
}

// ---------------- kernel 1: weight transpose (coalesced 32x32 tiles) ----------------
__global__ void __launch_bounds__(256) wprep_kernel(const float* __restrict__ wcos,
                                                    const float* __restrict__ wsin) {
    __shared__ float sc[32][33];
    __shared__ float ss[32][33];
    const int kt = blockIdx.y * 32;
    const int jt = blockIdx.x * 32;
    const int tx = threadIdx.x & 31;
    const int ty = threadIdx.x >> 5;
#pragma unroll
    for (int tt = 0; tt < 4; ++tt) {
        int kl = ty * 4 + tt;
        size_t src = (size_t)(kt + kl) * NFFT + jt + tx + 1;
        sc[kl][tx] = tf32r(wcos[src]);
        ss[kl][tx] = tf32r(wsin[src]);
    }
    __syncthreads();
#pragma unroll
    for (int tt = 0; tt < 4; ++tt) {
        int jl = ty * 4 + tt;
        size_t dst = (size_t)(jt + jl) * MDIM + kt + tx;
        g_Wct[dst] = sc[tx][jl];
        g_Wst[dst] = ss[tx][jl];
    }
}

// ---------------- kernel 2: fused reflect-pad + fold + transpose ----------------
__global__ void __launch_bounds__(256) frame_kernel(const float* __restrict__ x) {
    __shared__ float su[32][33];
    __shared__ float sv[32][33];
    const int b  = blockIdx.z;
    const int t0 = blockIdx.x * 32;
    const int j0 = blockIdx.y * 32;
    const int tx = threadIdx.x & 31;
    const int ty = threadIdx.x >> 5;
    const float* __restrict__ xb = x + (size_t)b * LEN;

#pragma unroll
    for (int tt = 0; tt < 4; ++tt) {
        int tl = ty * 4 + tt;
        int t = t0 + tl;
        float u = 0.f, v = 0.f;
        if (t < NFRAMES) {
            int j = j0 + tx;
            int base = t * HOP - PADW;
            int m1 = base + j + 1;
            int m2 = base + 2047 - j;
            m1 = m1 < 0 ? -m1 : (m1 >= LEN ? 2 * LEN - 2 - m1 : m1);
            m2 = m2 < 0 ? -m2 : (m2 >= LEN ? 2 * LEN - 2 - m2 : m2);
            float a  = xb[m1];
            float bb = xb[m2];
            u = a + bb;
            v = a - bb;
            if (j == 1023) { u = a; v = 0.f; }
        }
        su[tl][tx] = tf32r(u);
        sv[tl][tx] = tf32r(v);
    }
    __syncthreads();

    int t = t0 + tx;
    if (t >= NFRAMES) return;
    int bt = b * NFRAMES + t;
#pragma unroll
    for (int jj = 0; jj < 4; ++jj) {
        int jl = ty * 4 + jj;
        int j = j0 + jl;
        g_Ut[(size_t)j * NPAD + bt] = su[tx][jl];
        g_Vt[(size_t)j * NPAD + bt] = sv[tx][jl];
    }
}

// ---------------- kernel 3: Nyquist bin k=1024, one warp per frame ----------------
__global__ void __launch_bounds__(256) nyq_kernel(const float* __restrict__ x,
                                                  const float* __restrict__ wcos,
                                                  const float* __restrict__ wsin,
                                                  float* __restrict__ out) {
    __shared__ float wc[NFFT];
    __shared__ float ws[NFFT];
    for (int i = threadIdx.x; i < NFFT; i += 256) {
        wc[i] = wcos[(size_t)1024 * NFFT + i];
        ws[i] = wsin[(size_t)1024 * NFFT + i];
    }
    __syncthreads();
    const int lane = threadIdx.x & 31;
    const int bt = blockIdx.x * 8 + (threadIdx.x >> 5);
    if (bt >= NBT) return;
    int b = bt / NFRAMES;
    int t = bt - b * NFRAMES;
    const float* __restrict__ xb = x + (size_t)b * LEN;
    int base = t * HOP - PADW;
    float sr = 0.f, si = 0.f;
#pragma unroll 4
    for (int s = lane; s < NFFT; s += 32) {
        int m = base + s;
        m = m < 0 ? -m : (m >= LEN ? 2 * LEN - 2 - m : m);
        float f = xb[m];
        sr += wc[s] * f;
        si += ws[s] * f;
    }
#pragma unroll
    for (int o = 16; o > 0; o >>= 1) {
        sr += __shfl_xor_sync(0xffffffffu, sr, o);
        si += __shfl_xor_sync(0xffffffffu, si, o);
    }
    if (lane == 0) {
        size_t o = (((size_t)b * FREQ + 1024) * NFRAMES + t) << 1;
        out[o]     = sr;
        out[o + 1] = -si;
    }
}

// ---------------- kernel 4: TF32 GEMM, 128x128 tile, 4 warps x (64x64), 5-stage ----------------
#define MMA_TF32(d, a, b)                                                       \
    asm volatile(                                                               \
        "mma.sync.aligned.m16n8k8.row.col.f32.tf32.tf32.f32 "                   \
        "{%0,%1,%2,%3},{%4,%5,%6,%7},{%8,%9},{%0,%1,%2,%3};"                    \
        : "+f"(d[0]), "+f"(d[1]), "+f"(d[2]), "+f"(d[3])                        \
        : "r"(a[0]), "r"(a[1]), "r"(a[2]), "r"(a[3]), "r"(b[0]), "r"(b[1]))

__global__ void __launch_bounds__(128, 2) gemm_kernel(float* __restrict__ out) {
    extern __shared__ float smem[];
    const int z = blockIdx.z;
    const float* __restrict__ W = z ? g_Wst : g_Wct;
    const float* __restrict__ X = z ? g_Vt  : g_Ut;

    const int tid  = threadIdx.x;
    const int warp = tid >> 5, lane = tid & 31;
    const int wm = warp & 1;            // 0..1 : 64-row slabs
    const int wn = warp >> 1;           // 0..1 : 64-col slabs
    const int g  = lane >> 2;
    const int tg = lane & 3;
    // m is the FAST block index -> concurrent CTAs share B n-tiles (L2 reuse)
    const int m0 = blockIdx.x * 128;
    const int n0 = blockIdx.y * 128;

    // cp.async: 128 threads cover A(16x128) + B(16x128): rows rS+4p, p=0..3
    const int rS = tid >> 5;            // 0..3
    const int cS = (tid & 31) * 4;      // 0..124
    const float* Abase = W + m0 + cS;
    const float* Bbase = X + n0 + cS;

    const uint32_t sbase = (uint32_t)__cvta_generic_to_shared(smem);

    auto issue = [&](int c, int slot) {
        size_t koff = (size_t)c * 16;
        uint32_t sb = sbase + (uint32_t)(slot * STAGE_FLOATS * 4);
#pragma unroll
        for (int p = 0; p < 4; ++p) {
            int row = rS + 4 * p;
            cpa16(sb + (uint32_t)((row * SSTR + cS) * 4),
                  Abase + (koff + row) * MDIM);
            cpa16(sb + (uint32_t)(((16 + row) * SSTR + cS) * 4),
                  Bbase + (koff + row) * NPAD);
        }
        cpa_commit();
    };

    float acc[4][8][4];
#pragma unroll
    for (int i = 0; i < 4; ++i)
#pragma unroll
        for (int j = 0; j < 8; ++j)
#pragma unroll
            for (int c = 0; c < 4; ++c) acc[i][j][c] = 0.f;

    const int abase = wm * 64 + g;
    const int bbase = wn * 64 + g;

#pragma unroll
    for (int p = 0; p < STAGES - 1; ++p) issue(p, p);

    int slot = 0;
    int islot = STAGES - 1;
    for (int c = 0; c < NKT; ++c) {
        const int rem = NKT - 1 - c;
        if (rem >= 3)      cpa_wait<3>();
        else if (rem == 2) cpa_wait<2>();
        else if (rem == 1) cpa_wait<1>();
        else               cpa_wait<0>();
        __syncthreads();
        if (c + STAGES - 1 < NKT) issue(c + STAGES - 1, islot);

        const uint32_t* Asu = (const uint32_t*)(smem + slot * STAGE_FLOATS);
        const uint32_t* Bsu = Asu + 16 * SSTR;
#pragma unroll
        for (int s = 0; s < 2; ++s) {
            const int krow = 8 * s + tg;
            uint32_t bf[8][2];
#pragma unroll
            for (int j = 0; j < 8; ++j) {
                bf[j][0] = Bsu[krow * SSTR + bbase + 8 * j];
                bf[j][1] = Bsu[(krow + 4) * SSTR + bbase + 8 * j];
            }
#pragma unroll
            for (int i = 0; i < 4; ++i) {
                uint32_t af[4];
                const int mcol = abase + 16 * i;
                af[0] = Asu[krow * SSTR + mcol];
                af[1] = Asu[krow * SSTR + mcol + 8];
                af[2] = Asu[(krow + 4) * SSTR + mcol];
                af[3] = Asu[(krow + 4) * SSTR + mcol + 8];
#pragma unroll
                for (int j = 0; j < 8; ++j) MMA_TF32(acc[i][j], af, bf[j]);
            }
        }
        slot  = (slot  == STAGES - 1) ? 0 : slot + 1;
        islot = (islot == STAGES - 1) ? 0 : islot + 1;
    }

    // epilogue: out[b][k][t][z], imag negated; k < 1024 always
    int btc[8][2], bc[8][2], tc[8][2];
#pragma unroll
    for (int j = 0; j < 8; ++j)
#pragma unroll
        for (int q = 0; q < 2; ++q) {
            int bt = n0 + wn * 64 + 8 * j + 2 * tg + q;
            btc[j][q] = bt;
            bc[j][q] = bt / NFRAMES;
            tc[j][q] = bt - bc[j][q] * NFRAMES;
        }
#pragma unroll
    for (int i = 0; i < 4; ++i) {
#pragma unroll
        for (int h = 0; h < 2; ++h) {
            int k = m0 + wm * 64 + 16 * i + g + 8 * h;
#pragma unroll
            for (int j = 0; j < 8; ++j)
#pragma unroll
                for (int q = 0; q < 2; ++q) {
                    if (btc[j][q] >= NBT) continue;
                    float v = acc[i][j][2 * h + q];
                    if (z) v = -v;
                    out[((((size_t)bc[j][q] * FREQ + k) * NFRAMES + tc[j][q]) << 1) + z] = v;
                }
        }
    }
}

// ---------------- launch ----------------
extern "C" void kernel_launch(void* const* d_in, const int* in_sizes, int n_in,
                              void* d_out, int out_size) {
    const float* x    = (const float*)d_in[0];
    const float* wcos = (const float*)d_in[1];
    const float* wsin = (const float*)d_in[2];
    float* out = (float*)d_out;

    cudaFuncSetAttribute(gemm_kernel, cudaFuncAttributeMaxDynamicSharedMemorySize, SMEM_BYTES);

    wprep_kernel<<<dim3(KDIM / 32, MDIM / 32), 256>>>(wcos, wsin);
    frame_kernel<<<dim3((NFRAMES + 31) / 32, KDIM / 32, BATCH), 256>>>(x);
    nyq_kernel<<<(NBT + 7) / 8, 256>>>(x, wcos, wsin, out);
    gemm_kernel<<<dim3(MDIM / 128, NPAD / 128, 2), 128, SMEM_BYTES>>>(out);
}

// round 14
// speedup vs baseline: 2.9172x; 1.5585x over previous
#include <cuda_runtime.h>
#include <cstdint>

// ---------------- problem constants ----------------
#define BATCH     32
#define LEN       220500
#define HOP       512
#define PADW      1024
#define FREQ      1025
#define NFRAMES   431
#define NBT       (BATCH * NFRAMES)     // 13792
#define NPAD      13824                 // 108 * 128
#define NFFT      2048
#define MLDA      512                   // W cols (k=0..511), GEMM M
#define KHALF     512                   // K per parity half
#define SSTR      136                   // smem row stride (floats)
#define NKT       (KHALF / 16)          // 32 k-tiles per GEMM
#define STAGES    5
#define STAGE_FLOATS (2 * 16 * SSTR)    // 4352 floats / stage
#define SMEM_BYTES (STAGES * STAGE_FLOATS * 4)   // 87040 B (2 CTAs/SM)

// ---------------- device scratch ----------------
// rows r: parity-permuted j (i=j+1): r<512 <-> i even ; r>=512 <-> i odd
__device__ float g_Ut [1024 * NPAD];
__device__ float g_Vt [1024 * NPAD];
__device__ float g_Wct[1024 * MLDA];
__device__ float g_Wst[1024 * MLDA];
__device__ float g_C  [4 * MLDA * NPAD];   // P+c, P-c, P+s, P-s

__device__ __forceinline__ float tf32r(float x) {
    uint32_t u; asm("cvt.rna.tf32.f32 %0, %1;" : "=r"(u) : "f"(x));
    return __uint_as_float(u);
}
__device__ __forceinline__ void cpa16(uint32_t s, const void* g) {
    asm volatile("cp.async.cg.shared.global [%0], [%1], 16;" :: "r"(s), "l"(g));
}
__device__ __forceinline__ void cpa_commit() {
    asm volatile("cp.async.commit_group;" ::: "memory");
}
template <int N>
__device__ __forceinline__ void cpa_wait() {
    asm volatile("cp.async.wait_group %0;" :: "n"(N) : "memory");
}
__device__ __forceinline__ int permrow(int j) {      // j in [0,1024)
    return (j & 1) ? (j >> 1) : 512 + (j >> 1);
}

// ---------------- kernel 1: weight transpose, k<512, parity-permuted rows ----------------
__global__ void __launch_bounds__(256) wprep_kernel(const float* __restrict__ wcos,
                                                    const float* __restrict__ wsin) {
    __shared__ float sc[32][33];
    __shared__ float ss[32][33];
    const int kt = blockIdx.y * 32;          // 0..480
    const int jt = blockIdx.x * 32;          // 0..992
    const int tx = threadIdx.x & 31;
    const int ty = threadIdx.x >> 5;
#pragma unroll
    for (int tt = 0; tt < 4; ++tt) {
        int kl = ty * 4 + tt;
        size_t src = (size_t)(kt + kl) * NFFT + jt + tx + 1;
        sc[kl][tx] = tf32r(wcos[src]);
        ss[kl][tx] = tf32r(wsin[src]);
    }
    __syncthreads();
#pragma unroll
    for (int tt = 0; tt < 4; ++tt) {
        int jl = ty * 4 + tt;
        int r = permrow(jt + jl);
        size_t dst = (size_t)r * MLDA + kt + tx;
        g_Wct[dst] = sc[tx][jl];
        g_Wst[dst] = ss[tx][jl];
    }
}

// ---------------- kernel 2: fused reflect-pad + fold + transpose (permuted rows) ----------------
__global__ void __launch_bounds__(256) frame_kernel(const float* __restrict__ x) {
    __shared__ float su[32][33];
    __shared__ float sv[32][33];
    const int b  = blockIdx.z;
    const int t0 = blockIdx.x * 32;
    const int j0 = blockIdx.y * 32;
    const int tx = threadIdx.x & 31;
    const int ty = threadIdx.x >> 5;
    const float* __restrict__ xb = x + (size_t)b * LEN;

#pragma unroll
    for (int tt = 0; tt < 4; ++tt) {
        int tl = ty * 4 + tt;
        int t = t0 + tl;
        float u = 0.f, v = 0.f;
        if (t < NFRAMES) {
            int j = j0 + tx;
            int base = t * HOP - PADW;
            int m1 = base + j + 1;
            int m2 = base + 2047 - j;
            m1 = m1 < 0 ? -m1 : (m1 >= LEN ? 2 * LEN - 2 - m1 : m1);
            m2 = m2 < 0 ? -m2 : (m2 >= LEN ? 2 * LEN - 2 - m2 : m2);
            float a  = xb[m1];
            float bb = xb[m2];
            u = a + bb;
            v = a - bb;
            if (j == 1023) { u = a; v = 0.f; }
        }
        su[tl][tx] = tf32r(u);
        sv[tl][tx] = tf32r(v);
    }
    __syncthreads();

    int t = t0 + tx;
    if (t >= NFRAMES) return;
    int bt = b * NFRAMES + t;
#pragma unroll
    for (int jj = 0; jj < 4; ++jj) {
        int jl = ty * 4 + jj;
        int r = permrow(j0 + jl);
        g_Ut[(size_t)r * NPAD + bt] = su[tx][jl];
        g_Vt[(size_t)r * NPAD + bt] = sv[tx][jl];
    }
}

// ---------------- kernel 3: exact k=512 row, one warp per frame ----------------
__global__ void __launch_bounds__(256) k512_kernel(const float* __restrict__ x,
                                                   const float* __restrict__ wcos,
                                                   const float* __restrict__ wsin,
                                                   float* __restrict__ out) {
    __shared__ float wc[NFFT];
    __shared__ float ws[NFFT];
    for (int i = threadIdx.x; i < NFFT; i += 256) {
        wc[i] = wcos[(size_t)512 * NFFT + i];
        ws[i] = wsin[(size_t)512 * NFFT + i];
    }
    __syncthreads();
    const int lane = threadIdx.x & 31;
    const int bt = blockIdx.x * 8 + (threadIdx.x >> 5);
    if (bt >= NBT) return;
    int b = bt / NFRAMES;
    int t = bt - b * NFRAMES;
    const float* __restrict__ xb = x + (size_t)b * LEN;
    int base = t * HOP - PADW;
    float sr = 0.f, si = 0.f;
#pragma unroll 4
    for (int s = lane; s < NFFT; s += 32) {
        int m = base + s;
        m = m < 0 ? -m : (m >= LEN ? 2 * LEN - 2 - m : m);
        float f = xb[m];
        sr += wc[s] * f;
        si += ws[s] * f;
    }
#pragma unroll
    for (int o = 16; o > 0; o >>= 1) {
        sr += __shfl_xor_sync(0xffffffffu, sr, o);
        si += __shfl_xor_sync(0xffffffffu, si, o);
    }
    if (lane == 0) {
        size_t o = (((size_t)b * FREQ + 512) * NFRAMES + t) << 1;
        out[o]     = sr;
        out[o + 1] = -si;
    }
}

// ---------------- kernel 4: TF32 GEMM, M=512 K=512, z=(cos/sin)x(even/odd) ----------------
#define MMA_TF32(d, a, b)                                                       \
    asm volatile(                                                               \
        "mma.sync.aligned.m16n8k8.row.col.f32.tf32.tf32.f32 "                   \
        "{%0,%1,%2,%3},{%4,%5,%6,%7},{%8,%9},{%0,%1,%2,%3};"                    \
        : "+f"(d[0]), "+f"(d[1]), "+f"(d[2]), "+f"(d[3])                        \
        : "r"(a[0]), "r"(a[1]), "r"(a[2]), "r"(a[3]), "r"(b[0]), "r"(b[1]))

__global__ void __launch_bounds__(128, 2) gemm_kernel() {
    extern __shared__ float smem[];
    const int z = blockIdx.z;                       // 0:P+c 1:P-c 2:P+s 3:P-s
    const float* __restrict__ W = (z < 2 ? g_Wct : g_Wst) + (size_t)(z & 1) * 512 * MLDA;
    const float* __restrict__ X = (z < 2 ? g_Ut  : g_Vt ) + (size_t)(z & 1) * 512 * NPAD;
    float* __restrict__ C = g_C + (size_t)z * MLDA * NPAD;

    const int tid  = threadIdx.x;
    const int warp = tid >> 5, lane = tid & 31;
    const int wm = warp & 1;
    const int wn = warp >> 1;
    const int g  = lane >> 2;
    const int tg = lane & 3;
    const int m0 = blockIdx.x * 128;                // m fast -> B L2 reuse
    const int n0 = blockIdx.y * 128;

    const int rS = tid >> 5;
    const int cS = (tid & 31) * 4;
    const float* Abase = W + m0 + cS;
    const float* Bbase = X + n0 + cS;

    const uint32_t sbase = (uint32_t)__cvta_generic_to_shared(smem);

    auto issue = [&](int c, int slot) {
        size_t koff = (size_t)c * 16;
        uint32_t sb = sbase + (uint32_t)(slot * STAGE_FLOATS * 4);
#pragma unroll
        for (int p = 0; p < 4; ++p) {
            int row = rS + 4 * p;
            cpa16(sb + (uint32_t)((row * SSTR + cS) * 4),
                  Abase + (koff + row) * MLDA);
            cpa16(sb + (uint32_t)(((16 + row) * SSTR + cS) * 4),
                  Bbase + (koff + row) * NPAD);
        }
        cpa_commit();
    };

    float acc[4][8][4];
#pragma unroll
    for (int i = 0; i < 4; ++i)
#pragma unroll
        for (int j = 0; j < 8; ++j)
#pragma unroll
            for (int c = 0; c < 4; ++c) acc[i][j][c] = 0.f;

    const int abase = wm * 64 + g;
    const int bbase = wn * 64 + g;

#pragma unroll
    for (int p = 0; p < STAGES - 1; ++p) issue(p, p);

    int slot = 0;
    int islot = STAGES - 1;
    for (int c = 0; c < NKT; ++c) {
        const int rem = NKT - 1 - c;
        if (rem >= 3)      cpa_wait<3>();
        else if (rem == 2) cpa_wait<2>();
        else if (rem == 1) cpa_wait<1>();
        else               cpa_wait<0>();
        __syncthreads();
        if (c + STAGES - 1 < NKT) issue(c + STAGES - 1, islot);

        const uint32_t* Asu = (const uint32_t*)(smem + slot * STAGE_FLOATS);
        const uint32_t* Bsu = Asu + 16 * SSTR;
#pragma unroll
        for (int s = 0; s < 2; ++s) {
            const int krow = 8 * s + tg;
            uint32_t bf[8][2];
#pragma unroll
            for (int j = 0; j < 8; ++j) {
                bf[j][0] = Bsu[krow * SSTR + bbase + 8 * j];
                bf[j][1] = Bsu[(krow + 4) * SSTR + bbase + 8 * j];
            }
#pragma unroll
            for (int i = 0; i < 4; ++i) {
                uint32_t af[4];
                const int mcol = abase + 16 * i;
                af[0] = Asu[krow * SSTR + mcol];
                af[1] = Asu[krow * SSTR + mcol + 8];
                af[2] = Asu[(krow + 4) * SSTR + mcol];
                af[3] = Asu[(krow + 4) * SSTR + mcol + 8];
#pragma unroll
                for (int j = 0; j < 8; ++j) MMA_TF32(acc[i][j], af, bf[j]);
            }
        }
        slot  = (slot  == STAGES - 1) ? 0 : slot + 1;
        islot = (islot == STAGES - 1) ? 0 : islot + 1;
    }

    // epilogue: dense scratch C[k][bt], float2 stores (bt even-aligned)
#pragma unroll
    for (int i = 0; i < 4; ++i)
#pragma unroll
        for (int h = 0; h < 2; ++h) {
            int k = m0 + wm * 64 + 16 * i + g + 8 * h;   // < 512
#pragma unroll
            for (int j = 0; j < 8; ++j) {
                int bt = n0 + wn * 64 + 8 * j + 2 * tg;
                float2 st = make_float2(acc[i][j][2 * h], acc[i][j][2 * h + 1]);
                *(float2*)&C[(size_t)k * NPAD + bt] = st;
            }
        }
}

// ---------------- kernel 5: combine P+/P- -> out[k] and out[1024-k] ----------------
__global__ void __launch_bounds__(256) combine_kernel(float* __restrict__ out) {
    const int k  = blockIdx.y;                        // 0..511
    const int bt = blockIdx.x * 256 + threadIdx.x;
    if (bt >= NBT) return;
    const size_t base = (size_t)k * NPAD + bt;
    const size_t ZS = (size_t)MLDA * NPAD;
    float c0 = g_C[base];            // P+c
    float c1 = g_C[base + ZS];       // P-c
    float c2 = g_C[base + 2 * ZS];   // P+s
    float c3 = g_C[base + 3 * ZS];   // P-s
    int b = bt / NFRAMES;
    int t = bt - b * NFRAMES;
    size_t o1 = ((size_t)b * FREQ + k) * NFRAMES + t;
    size_t o2 = ((size_t)b * FREQ + (1024 - k)) * NFRAMES + t;
    ((float2*)out)[o1] = make_float2(c0 + c1, -(c2 + c3));
    ((float2*)out)[o2] = make_float2(c0 - c1, c2 - c3);
}

// ---------------- launch ----------------
extern "C" void kernel_launch(void* const* d_in, const int* in_sizes, int n_in,
                              void* d_out, int out_size) {
    const float* x    = (const float*)d_in[0];
    const float* wcos = (const float*)d_in[1];
    const float* wsin = (const float*)d_in[2];
    float* out = (float*)d_out;

    cudaFuncSetAttribute(gemm_kernel, cudaFuncAttributeMaxDynamicSharedMemorySize, SMEM_BYTES);

    wprep_kernel<<<dim3(1024 / 32, MLDA / 32), 256>>>(wcos, wsin);
    frame_kernel<<<dim3((NFRAMES + 31) / 32, 1024 / 32, BATCH), 256>>>(x);
    k512_kernel<<<(NBT + 7) / 8, 256>>>(x, wcos, wsin, out);
    gemm_kernel<<<dim3(MLDA / 128, NPAD / 128, 4), 128, SMEM_BYTES>>>();
    combine_kernel<<<dim3((NBT + 255) / 256, MLDA), 256>>>(out);
}

// round 15
// speedup vs baseline: 4.2379x; 1.4527x over previous
#include <cuda_runtime.h>
#include <cuda_fp16.h>
#include <cstdint>

// ---------------- problem constants ----------------
#define BATCH     32
#define LEN       220500
#define HOP       512
#define PADW      1024
#define FREQ      1025
#define NFRAMES   431
#define NBT       (BATCH * NFRAMES)     // 13792
#define NPAD      13824                 // 108 * 128
#define NFFT      2048
#define MLDA      512                   // GEMM M (k-bins 0..511)
#define KP        256                   // k-pair rows per parity half (512 k / 2)
#define SSTR      136                   // smem row stride (u32 words) -> conflict-free
#define NKT       (KP / 16)             // 16 k-tiles (each = 32 k)
#define STAGES    5
#define STAGE_WORDS (2 * 16 * SSTR)     // A+B per stage = 4352 u32 (17408 B)
#define SMEM_BYTES (STAGES * STAGE_WORDS * 4)    // 87040 B (2 CTAs/SM)

// ---------------- device scratch ----------------
// half2-packed along K: word [h][kp][col] = {val(k=2kp), val(k=2kp+1)}
// halves: h=0 <-> odd j (even i=j+1, "P+"), h=1 <-> even j ("P-")
__device__ unsigned g_W16c[2 * KP * MLDA];
__device__ unsigned g_W16s[2 * KP * MLDA];
__device__ unsigned g_U16 [2 * KP * NPAD];
__device__ unsigned g_V16 [2 * KP * NPAD];
__device__ float    g_C   [4 * MLDA * NPAD];   // P+c, P-c, P+s, P-s

__device__ __forceinline__ void cpa16(uint32_t s, const void* g) {
    asm volatile("cp.async.cg.shared.global [%0], [%1], 16;" :: "r"(s), "l"(g));
}
__device__ __forceinline__ void cpa_commit() {
    asm volatile("cp.async.commit_group;" ::: "memory");
}
template <int N>
__device__ __forceinline__ void cpa_wait() {
    asm volatile("cp.async.wait_group %0;" :: "n"(N) : "memory");
}
__device__ __forceinline__ unsigned packh2(float lo, float hi) {
    __half2 h = __floats2half2_rn(lo, hi);   // .x = lo (k even), .y = hi (k odd)
    return *(unsigned*)&h;
}

// ---------------- kernel 1: weight transpose + fp16 K-pair pack ----------------
__global__ void __launch_bounds__(256) wprep_kernel(const float* __restrict__ wcos,
                                                    const float* __restrict__ wsin) {
    __shared__ float sc[32][33];
    __shared__ float ss[32][33];
    const int kt = blockIdx.y * 32;          // bin tile: 0..480
    const int jt = blockIdx.x * 32;          // j tile:  0..992
    const int tx = threadIdx.x & 31;
    const int ty = threadIdx.x >> 5;
#pragma unroll
    for (int tt = 0; tt < 4; ++tt) {
        int kl = ty * 4 + tt;
        size_t src = (size_t)(kt + kl) * NFFT + jt + tx + 1;
        sc[kl][tx] = wcos[src];
        ss[kl][tx] = wsin[src];
    }
    __syncthreads();
#pragma unroll
    for (int tt = 0; tt < 2; ++tt) {
        int jl = ty * 4 + tt;                // pairs (jl, jl+2): same parity, K-adjacent
        int j  = jt + jl;
        int h  = (j & 1) ? 0 : 1;
        int kp = (j >> 1) >> 1;              // (jt+ty*4) is 4-aligned -> exact pair
        size_t dst = ((size_t)h * KP + kp) * MLDA + kt + tx;
        g_W16c[dst] = packh2(sc[tx][jl], sc[tx][jl + 2]);
        g_W16s[dst] = packh2(ss[tx][jl], ss[tx][jl + 2]);
    }
}

// ---------------- kernel 2: fused reflect-pad + fold + transpose + fp16 pack ----------------
__global__ void __launch_bounds__(256) frame_kernel(const float* __restrict__ x) {
    __shared__ float su[32][33];
    __shared__ float sv[32][33];
    const int b  = blockIdx.z;
    const int t0 = blockIdx.x * 32;
    const int j0 = blockIdx.y * 32;
    const int tx = threadIdx.x & 31;
    const int ty = threadIdx.x >> 5;
    const float* __restrict__ xb = x + (size_t)b * LEN;

#pragma unroll
    for (int tt = 0; tt < 4; ++tt) {
        int tl = ty * 4 + tt;
        int t = t0 + tl;
        float u = 0.f, v = 0.f;
        if (t < NFRAMES) {
            int j = j0 + tx;
            int base = t * HOP - PADW;
            int m1 = base + j + 1;
            int m2 = base + 2047 - j;
            m1 = m1 < 0 ? -m1 : (m1 >= LEN ? 2 * LEN - 2 - m1 : m1);
            m2 = m2 < 0 ? -m2 : (m2 >= LEN ? 2 * LEN - 2 - m2 : m2);
            float a  = xb[m1];
            float bb = xb[m2];
            u = a + bb;
            v = a - bb;
            if (j == 1023) { u = a; v = 0.f; }
        }
        su[tl][tx] = u;
        sv[tl][tx] = v;
    }
    __syncthreads();

    int t = t0 + tx;
    if (t >= NFRAMES) return;
    int bt = b * NFRAMES + t;
#pragma unroll
    for (int tt = 0; tt < 2; ++tt) {
        int jl = ty * 4 + tt;
        int j  = j0 + jl;
        int h  = (j & 1) ? 0 : 1;
        int kp = (j >> 1) >> 1;
        size_t dst = ((size_t)h * KP + kp) * NPAD + bt;
        g_U16[dst] = packh2(su[tx][jl], su[tx][jl + 2]);
        g_V16[dst] = packh2(sv[tx][jl], sv[tx][jl + 2]);
    }
}

// ---------------- kernel 3: exact k=512 row (fp32), one warp per frame ----------------
__global__ void __launch_bounds__(256) k512_kernel(const float* __restrict__ x,
                                                   const float* __restrict__ wcos,
                                                   const float* __restrict__ wsin,
                                                   float* __restrict__ out) {
    __shared__ float wc[NFFT];
    __shared__ float ws[NFFT];
    for (int i = threadIdx.x; i < NFFT; i += 256) {
        wc[i] = wcos[(size_t)512 * NFFT + i];
        ws[i] = wsin[(size_t)512 * NFFT + i];
    }
    __syncthreads();
    const int lane = threadIdx.x & 31;
    const int bt = blockIdx.x * 8 + (threadIdx.x >> 5);
    if (bt >= NBT) return;
    int b = bt / NFRAMES;
    int t = bt - b * NFRAMES;
    const float* __restrict__ xb = x + (size_t)b * LEN;
    int base = t * HOP - PADW;
    float sr = 0.f, si = 0.f;
#pragma unroll 4
    for (int s = lane; s < NFFT; s += 32) {
        int m = base + s;
        m = m < 0 ? -m : (m >= LEN ? 2 * LEN - 2 - m : m);
        float f = xb[m];
        sr += wc[s] * f;
        si += ws[s] * f;
    }
#pragma unroll
    for (int o = 16; o > 0; o >>= 1) {
        sr += __shfl_xor_sync(0xffffffffu, sr, o);
        si += __shfl_xor_sync(0xffffffffu, si, o);
    }
    if (lane == 0) {
        size_t o = (((size_t)b * FREQ + 512) * NFRAMES + t) << 1;
        out[o]     = sr;
        out[o + 1] = -si;
    }
}

// ---------------- kernel 4: FP16 m16n8k16 GEMM, M=512 Kh=512, z in {0..3} ----------------
#define MMA_F16(d, a, b)                                                        \
    asm volatile(                                                               \
        "mma.sync.aligned.m16n8k16.row.col.f32.f16.f16.f32 "                    \
        "{%0,%1,%2,%3},{%4,%5,%6,%7},{%8,%9},{%0,%1,%2,%3};"                    \
        : "+f"(d[0]), "+f"(d[1]), "+f"(d[2]), "+f"(d[3])                        \
        : "r"(a[0]), "r"(a[1]), "r"(a[2]), "r"(a[3]), "r"(b[0]), "r"(b[1]))

__global__ void __launch_bounds__(128, 2) gemm_kernel() {
    extern __shared__ unsigned smem[];
    const int z = blockIdx.z;                        // 0:P+c 1:P-c 2:P+s 3:P-s
    const unsigned* __restrict__ W = (z < 2 ? g_W16c : g_W16s) + (size_t)(z & 1) * KP * MLDA;
    const unsigned* __restrict__ X = (z < 2 ? g_U16  : g_V16 ) + (size_t)(z & 1) * KP * NPAD;
    float* __restrict__ C = g_C + (size_t)z * MLDA * NPAD;

    const int tid  = threadIdx.x;
    const int warp = tid >> 5, lane = tid & 31;
    const int wm = warp & 1;
    const int wn = warp >> 1;
    const int g  = lane >> 2;
    const int tg = lane & 3;
    const int m0 = blockIdx.x * 128;                 // m fast -> B L2 reuse
    const int n0 = blockIdx.y * 128;

    const int rS = tid >> 5;                         // 0..3
    const int cS = (tid & 31) * 4;                   // 0..124 (u32)
    const unsigned* Abase = W + m0 + cS;
    const unsigned* Bbase = X + n0 + cS;

    const uint32_t sbase = (uint32_t)__cvta_generic_to_shared(smem);

    auto issue = [&](int c, int slot) {
        size_t koff = (size_t)c * 16;                // 16 kp-rows per stage
        uint32_t sb = sbase + (uint32_t)(slot * STAGE_WORDS * 4);
#pragma unroll
        for (int p = 0; p < 4; ++p) {
            int row = rS + 4 * p;
            cpa16(sb + (uint32_t)((row * SSTR + cS) * 4),
                  Abase + (koff + row) * MLDA);
            cpa16(sb + (uint32_t)(((16 + row) * SSTR + cS) * 4),
                  Bbase + (koff + row) * NPAD);
        }
        cpa_commit();
    };

    float acc[4][8][4];
#pragma unroll
    for (int i = 0; i < 4; ++i)
#pragma unroll
        for (int j = 0; j < 8; ++j)
#pragma unroll
            for (int c = 0; c < 4; ++c) acc[i][j][c] = 0.f;

    const int abase = wm * 64 + g;
    const int bbase = wn * 64 + g;

#pragma unroll
    for (int p = 0; p < STAGES - 1; ++p) issue(p, p);

    int slot = 0;
    int islot = STAGES - 1;
    for (int c = 0; c < NKT; ++c) {
        const int rem = NKT - 1 - c;
        if (rem >= 3)      cpa_wait<3>();
        else if (rem == 2) cpa_wait<2>();
        else if (rem == 1) cpa_wait<1>();
        else               cpa_wait<0>();
        __syncthreads();
        if (c + STAGES - 1 < NKT) issue(c + STAGES - 1, islot);

        const unsigned* Asu = smem + slot * STAGE_WORDS;
        const unsigned* Bsu = Asu + 16 * SSTR;
#pragma unroll
        for (int s = 0; s < 2; ++s) {                // two k16 steps per stage
            const int kr0 = 8 * s + tg;              // kp rows tg, tg+4 in this group
            const int kr1 = kr0 + 4;
            uint32_t bf[8][2];
#pragma unroll
            for (int j = 0; j < 8; ++j) {
                bf[j][0] = Bsu[kr0 * SSTR + bbase + 8 * j];
                bf[j][1] = Bsu[kr1 * SSTR + bbase + 8 * j];
            }
#pragma unroll
            for (int i = 0; i < 4; ++i) {
                uint32_t af[4];
                const int mcol = abase + 16 * i;
                af[0] = Asu[kr0 * SSTR + mcol];
                af[1] = Asu[kr0 * SSTR + mcol + 8];
                af[2] = Asu[kr1 * SSTR + mcol];
                af[3] = Asu[kr1 * SSTR + mcol + 8];
#pragma unroll
                for (int j = 0; j < 8; ++j) MMA_F16(acc[i][j], af, bf[j]);
            }
        }
        slot  = (slot  == STAGES - 1) ? 0 : slot + 1;
        islot = (islot == STAGES - 1) ? 0 : islot + 1;
    }

    // epilogue: dense scratch C[k][bt], float2 stores
#pragma unroll
    for (int i = 0; i < 4; ++i)
#pragma unroll
        for (int h = 0; h < 2; ++h) {
            int k = m0 + wm * 64 + 16 * i + g + 8 * h;   // < 512
#pragma unroll
            for (int j = 0; j < 8; ++j) {
                int bt = n0 + wn * 64 + 8 * j + 2 * tg;
                float2 st = make_float2(acc[i][j][2 * h], acc[i][j][2 * h + 1]);
                *(float2*)&C[(size_t)k * NPAD + bt] = st;
            }
        }
}

// ---------------- kernel 5: combine P+/P- -> out[k] and out[1024-k] ----------------
__global__ void __launch_bounds__(256) combine_kernel(float* __restrict__ out) {
    const int k  = blockIdx.y;                        // 0..511
    const int bt = blockIdx.x * 256 + threadIdx.x;
    if (bt >= NBT) return;
    const size_t base = (size_t)k * NPAD + bt;
    const size_t ZS = (size_t)MLDA * NPAD;
    float c0 = g_C[base];            // P+c (even i)
    float c1 = g_C[base + ZS];       // P-c
    float c2 = g_C[base + 2 * ZS];   // P+s
    float c3 = g_C[base + 3 * ZS];   // P-s
    int b = bt / NFRAMES;
    int t = bt - b * NFRAMES;
    size_t o1 = ((size_t)b * FREQ + k) * NFRAMES + t;
    size_t o2 = ((size_t)b * FREQ + (1024 - k)) * NFRAMES + t;
    ((float2*)out)[o1] = make_float2(c0 + c1, -(c2 + c3));
    ((float2*)out)[o2] = make_float2(c0 - c1, c2 - c3);
}

// ---------------- launch ----------------
extern "C" void kernel_launch(void* const* d_in, const int* in_sizes, int n_in,
                              void* d_out, int out_size) {
    const float* x    = (const float*)d_in[0];
    const float* wcos = (const float*)d_in[1];
    const float* wsin = (const float*)d_in[2];
    float* out = (float*)d_out;

    cudaFuncSetAttribute(gemm_kernel, cudaFuncAttributeMaxDynamicSharedMemorySize, SMEM_BYTES);

    wprep_kernel<<<dim3(1024 / 32, MLDA / 32), 256>>>(wcos, wsin);
    frame_kernel<<<dim3((NFRAMES + 31) / 32, 1024 / 32, BATCH), 256>>>(x);
    k512_kernel<<<(NBT + 7) / 8, 256>>>(x, wcos, wsin, out);
    gemm_kernel<<<dim3(MLDA / 128, NPAD / 128, 4), 128, SMEM_BYTES>>>();
    combine_kernel<<<dim3((NBT + 255) / 256, MLDA), 256>>>(out);
}